// round 12
// baseline (speedup 1.0000x reference)
#include <cuda_runtime.h>
#include <math.h>
#include <stdint.h>

// ---------------------------------------------------------------------------
// CausalShapedAttention
//   1) qkv = x @ W_attn^T + b_attn   (tf32 tensor-core GEMM NT, 4096x3072x1024)
//   2) flash-style causal attention per head, fused "shaped" epilogue (fp32)
//   3) out = y @ W_proj^T + b_proj   (tf32 tensor-core GEMM NT, 4096x1024x1024)
// ---------------------------------------------------------------------------

#define BB 2
#define TT 2048
#define CC 1024
#define HH 16
#define DD 64

__device__ float g_qkv[(size_t)BB * TT * 3 * CC];
__device__ float g_y[(size_t)BB * TT * CC];

__device__ __forceinline__ uint32_t f2tf32(float x) {
    uint32_t r;
    asm("cvt.rna.tf32.f32 %0, %1;" : "=r"(r) : "f"(x));
    return r;
}

__device__ __forceinline__ void mma_tf32(float c[4], const uint32_t a[4],
                                         const uint32_t b[2]) {
    asm volatile(
        "mma.sync.aligned.m16n8k8.row.col.f32.tf32.tf32.f32 "
        "{%0,%1,%2,%3}, {%4,%5,%6,%7}, {%8,%9}, {%0,%1,%2,%3};"
        : "+f"(c[0]), "+f"(c[1]), "+f"(c[2]), "+f"(c[3])
        : "r"(a[0]), "r"(a[1]), "r"(a[2]), "r"(a[3]), "r"(b[0]), "r"(b[1]));
}

// ---------------------------------------------------------------------------
// tf32 GEMM NT:  C[M,N] = A[M,K] @ B[N,K]^T + bias[N]
// 128x128 block tile, BK=32, 256 threads = 8 warps (4 in M x 2 in N),
// warp tile 32x64, mma m16n8k8. M%128==0, N%128==0, K%32==0 here.
// ---------------------------------------------------------------------------
__global__ void __launch_bounds__(256) tf32_gemm_nt(
    const float* __restrict__ A, const float* __restrict__ B,
    const float* __restrict__ bias, float* __restrict__ C,
    int M, int N, int K)
{
    __shared__ uint32_t As[128][36];   // [m][k], pad 36 -> conflict-free frags
    __shared__ uint32_t Bs[128][36];   // [n][k]

    const int tid = threadIdx.x;
    const int m0 = blockIdx.y * 128;
    const int n0 = blockIdx.x * 128;
    const int warpId = tid >> 5;
    const int lane = tid & 31;
    const int g = lane >> 2;          // 0..7
    const int t = lane & 3;           // 0..3
    const int wm = (warpId & 3) * 32; // warp M offset in tile
    const int wn = (warpId >> 2) * 64;// warp N offset in tile

    const int ldRow = tid >> 3;       // 0..31
    const int ldCol = (tid & 7) * 4;  // 0,4,...,28

    const float* Ap = A + (size_t)m0 * K;
    const float* Bp = B + (size_t)n0 * K;

    float c[2][8][4];
#pragma unroll
    for (int mt = 0; mt < 2; mt++)
#pragma unroll
        for (int nt = 0; nt < 8; nt++)
#pragma unroll
            for (int j = 0; j < 4; j++) c[mt][nt][j] = 0.0f;

    for (int k0 = 0; k0 < K; k0 += 32) {
        float4 av[4], bv[4];
#pragma unroll
        for (int r = 0; r < 4; r++) {
            av[r] = *(const float4*)(Ap + (size_t)(ldRow + 32 * r) * K + k0 + ldCol);
            bv[r] = *(const float4*)(Bp + (size_t)(ldRow + 32 * r) * K + k0 + ldCol);
        }
        __syncthreads();
#pragma unroll
        for (int r = 0; r < 4; r++) {
            uint4 at, bt;
            at.x = f2tf32(av[r].x); at.y = f2tf32(av[r].y);
            at.z = f2tf32(av[r].z); at.w = f2tf32(av[r].w);
            bt.x = f2tf32(bv[r].x); bt.y = f2tf32(bv[r].y);
            bt.z = f2tf32(bv[r].z); bt.w = f2tf32(bv[r].w);
            *(uint4*)&As[ldRow + 32 * r][ldCol] = at;
            *(uint4*)&Bs[ldRow + 32 * r][ldCol] = bt;
        }
        __syncthreads();

#pragma unroll
        for (int kk = 0; kk < 4; kk++) {
            const int k = kk * 8;
            uint32_t a[2][4], b[8][2];
#pragma unroll
            for (int mt = 0; mt < 2; mt++) {
                const int rb = wm + mt * 16;
                a[mt][0] = As[rb + g][k + t];
                a[mt][1] = As[rb + g + 8][k + t];
                a[mt][2] = As[rb + g][k + t + 4];
                a[mt][3] = As[rb + g + 8][k + t + 4];
            }
#pragma unroll
            for (int nt = 0; nt < 8; nt++) {
                const int nb = wn + nt * 8;
                b[nt][0] = Bs[nb + g][k + t];
                b[nt][1] = Bs[nb + g][k + t + 4];
            }
#pragma unroll
            for (int mt = 0; mt < 2; mt++)
#pragma unroll
                for (int nt = 0; nt < 8; nt++)
                    mma_tf32(c[mt][nt], a[mt], b[nt]);
        }
    }

    // epilogue: c frag layout — rows g / g+8, cols 2t / 2t+1
#pragma unroll
    for (int mt = 0; mt < 2; mt++) {
        const int r0 = m0 + wm + mt * 16 + g;
#pragma unroll
        for (int nt = 0; nt < 8; nt++) {
            const int col = n0 + wn + nt * 8 + 2 * t;
            const float b0 = bias[col], b1 = bias[col + 1];
            float2 o0 = make_float2(c[mt][nt][0] + b0, c[mt][nt][1] + b1);
            float2 o1 = make_float2(c[mt][nt][2] + b0, c[mt][nt][3] + b1);
            *(float2*)(C + (size_t)r0 * N + col) = o0;
            *(float2*)(C + (size_t)(r0 + 8) * N + col) = o1;
        }
    }
}

// ---------------------------------------------------------------------------
// Flash-style causal attention with fused "shaped" epilogue (unchanged fp32).
// Grid: (T/64, H, B). 128 threads: 16(tx) x 8(ty), micro-tile 8 rows x 4 cols.
// ---------------------------------------------------------------------------
__global__ void __launch_bounds__(128) attn_kernel(
    const float* __restrict__ qkv, float* __restrict__ y,
    const float* __restrict__ alpha_p, const float* __restrict__ beta_p,
    const float* __restrict__ gamma_p)
{
    extern __shared__ float sm[];
    float* Qs = sm;                  // 64 x 68
    float* Ks = sm + 64 * 68;        // 64 x 68
    float* Vs = sm + 2 * 64 * 68;    // 64 x 68
    float* Ps = sm + 3 * 64 * 68;    // 64 x 68

    const int qt = blockIdx.x;
    const int h  = blockIdx.y;
    const int b  = blockIdx.z;
    const int tid = threadIdx.x;
    const int tx = tid & 15;
    const int ty = tid >> 4;
    const int t0 = qt * 64;

    const float alpha = *alpha_p;
    const float beta  = *beta_p;
    const float gamma = *gamma_p;

    const size_t rs = 3 * CC;
    const float* qb = qkv + (size_t)b * TT * rs + h * DD;
    const float* kb = qb + CC;
    const float* vb = qb + 2 * CC;

    const int lr = tid >> 4;
    const int lc = (tid & 15) * 4;

#pragma unroll
    for (int it = 0; it < 8; it++) {
        int r = lr + it * 8;
        float4 qv = *(const float4*)(qb + (size_t)(t0 + r) * rs + lc);
        Qs[(lc + 0) * 68 + r] = qv.x;
        Qs[(lc + 1) * 68 + r] = qv.y;
        Qs[(lc + 2) * 68 + r] = qv.z;
        Qs[(lc + 3) * 68 + r] = qv.w;
    }

    float m[8], l[8], acc[8][4], vsf[4];
#pragma unroll
    for (int i = 0; i < 8; i++) { m[i] = -INFINITY; l[i] = 0.0f; }
#pragma unroll
    for (int i = 0; i < 8; i++)
#pragma unroll
        for (int j = 0; j < 4; j++) acc[i][j] = 0.0f;
    vsf[0] = vsf[1] = vsf[2] = vsf[3] = 0.0f;

    for (int kvt = 0; kvt <= qt; kvt++) {
        const bool diag = (kvt == qt);
        const int s0 = kvt * 64;

        __syncthreads();
#pragma unroll
        for (int it = 0; it < 8; it++) {
            int r = lr + it * 8;
            float4 kk = *(const float4*)(kb + (size_t)(s0 + r) * rs + lc);
            Ks[(lc + 0) * 68 + r] = kk.x;
            Ks[(lc + 1) * 68 + r] = kk.y;
            Ks[(lc + 2) * 68 + r] = kk.z;
            Ks[(lc + 3) * 68 + r] = kk.w;
            float4 vv = *(const float4*)(vb + (size_t)(s0 + r) * rs + lc);
            *(float4*)&Vs[r * 68 + lc] = vv;
        }
        __syncthreads();

        float S[8][4];
#pragma unroll
        for (int i = 0; i < 8; i++)
#pragma unroll
            for (int j = 0; j < 4; j++) S[i][j] = 0.0f;

#pragma unroll 16
        for (int dd = 0; dd < 64; dd++) {
            float4 a0 = *(const float4*)&Qs[dd * 68 + ty * 8];
            float4 a1 = *(const float4*)&Qs[dd * 68 + ty * 8 + 4];
            float4 bv = *(const float4*)&Ks[dd * 68 + tx * 4];
            float a[8] = {a0.x, a0.y, a0.z, a0.w, a1.x, a1.y, a1.z, a1.w};
#pragma unroll
            for (int i = 0; i < 8; i++) {
                S[i][0] = fmaf(a[i], bv.x, S[i][0]);
                S[i][1] = fmaf(a[i], bv.y, S[i][1]);
                S[i][2] = fmaf(a[i], bv.z, S[i][2]);
                S[i][3] = fmaf(a[i], bv.w, S[i][3]);
            }
        }

        const float scale = 0.125f;
#pragma unroll
        for (int i = 0; i < 8; i++)
#pragma unroll
            for (int j = 0; j < 4; j++) {
                float sv = S[i][j] * scale;
                if (diag && (tx * 4 + j > ty * 8 + i)) sv = -INFINITY;
                S[i][j] = sv;
            }

#pragma unroll
        for (int i = 0; i < 8; i++) {
            float rmax = fmaxf(fmaxf(S[i][0], S[i][1]), fmaxf(S[i][2], S[i][3]));
#pragma unroll
            for (int off = 8; off >= 1; off >>= 1)
                rmax = fmaxf(rmax, __shfl_xor_sync(0xffffffffu, rmax, off));
            float mnew = fmaxf(m[i], rmax);
            float corr = __expf(m[i] - mnew);
            float p0 = __expf(S[i][0] - mnew);
            float p1 = __expf(S[i][1] - mnew);
            float p2 = __expf(S[i][2] - mnew);
            float p3 = __expf(S[i][3] - mnew);
            float rsum = (p0 + p1) + (p2 + p3);
#pragma unroll
            for (int off = 8; off >= 1; off >>= 1)
                rsum += __shfl_xor_sync(0xffffffffu, rsum, off);
            l[i] = l[i] * corr + rsum;
            m[i] = mnew;
            acc[i][0] *= corr; acc[i][1] *= corr;
            acc[i][2] *= corr; acc[i][3] *= corr;
            Ps[(tx * 4 + 0) * 68 + ty * 8 + i] = p0;
            Ps[(tx * 4 + 1) * 68 + ty * 8 + i] = p1;
            Ps[(tx * 4 + 2) * 68 + ty * 8 + i] = p2;
            Ps[(tx * 4 + 3) * 68 + ty * 8 + i] = p3;
        }
        __syncthreads();

#pragma unroll 16
        for (int sl = 0; sl < 64; sl++) {
            float4 pa0 = *(const float4*)&Ps[sl * 68 + ty * 8];
            float4 pa1 = *(const float4*)&Ps[sl * 68 + ty * 8 + 4];
            float4 vv = *(const float4*)&Vs[sl * 68 + tx * 4];
            float p[8] = {pa0.x, pa0.y, pa0.z, pa0.w, pa1.x, pa1.y, pa1.z, pa1.w};
#pragma unroll
            for (int i = 0; i < 8; i++) {
                acc[i][0] = fmaf(p[i], vv.x, acc[i][0]);
                acc[i][1] = fmaf(p[i], vv.y, acc[i][1]);
                acc[i][2] = fmaf(p[i], vv.z, acc[i][2]);
                acc[i][3] = fmaf(p[i], vv.w, acc[i][3]);
            }
            if (!diag) {
                vsf[0] += vv.x; vsf[1] += vv.y; vsf[2] += vv.z; vsf[3] += vv.w;
            }
        }
    }

#pragma unroll
    for (int i = 0; i < 8; i++) {
        const int tl = ty * 8 + i;
        const int t  = t0 + tl;
        const float invl = 1.0f / l[i];
        const float invt = 1.0f / (float)(t + 1);
        float vdx = 0.0f, vdy = 0.0f, vdz = 0.0f, vdw = 0.0f;
        for (int sl = 0; sl <= tl; sl++) {
            float4 vv = *(const float4*)&Vs[sl * 68 + tx * 4];
            vdx += vv.x; vdy += vv.y; vdz += vv.z; vdw += vv.w;
        }
        float4 vself = *(const float4*)&Vs[tl * 68 + tx * 4];
        float4 o;
        o.x = beta * acc[i][0] * invl + alpha * vself.x - gamma * (vsf[0] + vdx) * invt;
        o.y = beta * acc[i][1] * invl + alpha * vself.y - gamma * (vsf[1] + vdy) * invt;
        o.z = beta * acc[i][2] * invl + alpha * vself.z - gamma * (vsf[2] + vdz) * invt;
        o.w = beta * acc[i][3] * invl + alpha * vself.w - gamma * (vsf[3] + vdw) * invt;
        *(float4*)(y + ((size_t)b * TT + t) * CC + h * DD + tx * 4) = o;
    }
}

// ---------------------------------------------------------------------------
extern "C" void kernel_launch(void* const* d_in, const int* in_sizes, int n_in,
                              void* d_out, int out_size)
{
    const float* x     = (const float*)d_in[0];
    const float* Wa    = (const float*)d_in[1];
    const float* ba    = (const float*)d_in[2];
    const float* Wp    = (const float*)d_in[3];
    const float* bp    = (const float*)d_in[4];
    const float* alpha = (const float*)d_in[5];
    const float* beta  = (const float*)d_in[6];
    const float* gamma = (const float*)d_in[7];
    float* out = (float*)d_out;

    float* qkv = nullptr;
    float* yb  = nullptr;
    cudaGetSymbolAddress((void**)&qkv, g_qkv);
    cudaGetSymbolAddress((void**)&yb,  g_y);

    const int smem = 4 * 64 * 68 * (int)sizeof(float);
    cudaFuncSetAttribute(attn_kernel,
                         cudaFuncAttributeMaxDynamicSharedMemorySize, smem);

    // 1) qkv = x @ W_attn^T + b_attn
    dim3 g1((3 * CC) / 128, (BB * TT) / 128);
    tf32_gemm_nt<<<g1, 256>>>(x, Wa, ba, qkv, BB * TT, 3 * CC, CC);

    // 2) shaped causal attention
    dim3 ga(TT / 64, HH, BB);
    attn_kernel<<<ga, 128, smem>>>(qkv, yb, alpha, beta, gamma);

    // 3) out = y @ W_proj^T + b_proj
    dim3 g2(CC / 128, (BB * TT) / 128);
    tf32_gemm_nt<<<g2, 256>>>(yb, Wp, bp, out, BB * TT, CC, CC);
}

// round 13
// speedup vs baseline: 1.0177x; 1.0177x over previous
#include <cuda_runtime.h>
#include <math.h>
#include <stdint.h>

// ---------------------------------------------------------------------------
// CausalShapedAttention
//   1) qkv = x @ W_attn^T + b_attn   (tf32 tensor-core GEMM NT, 4096x3072x1024)
//   2) flash-style causal attention per head, fused "shaped" epilogue (fp32)
//   3) out = y @ W_proj^T + b_proj   (tf32 tensor-core GEMM NT, 4096x1024x1024)
// ---------------------------------------------------------------------------

#define BB 2
#define TT 2048
#define CC 1024
#define HH 16
#define DD 64

__device__ float g_qkv[(size_t)BB * TT * 3 * CC];
__device__ float g_y[(size_t)BB * TT * CC];

__device__ __forceinline__ uint32_t f2tf32(float x) {
    uint32_t r;
    asm("cvt.rna.tf32.f32 %0, %1;" : "=r"(r) : "f"(x));
    return r;
}

__device__ __forceinline__ void mma_tf32(float c[4], const uint32_t a[4],
                                         const uint32_t b[2]) {
    asm volatile(
        "mma.sync.aligned.m16n8k8.row.col.f32.tf32.tf32.f32 "
        "{%0,%1,%2,%3}, {%4,%5,%6,%7}, {%8,%9}, {%0,%1,%2,%3};"
        : "+f"(c[0]), "+f"(c[1]), "+f"(c[2]), "+f"(c[3])
        : "r"(a[0]), "r"(a[1]), "r"(a[2]), "r"(a[3]), "r"(b[0]), "r"(b[1]));
}

// ---------------------------------------------------------------------------
// tf32 GEMM NT:  C[M,N] = A[M,K] @ B[N,K]^T + bias[N]
// 128x128 block tile, BK=32, 256 threads = 8 warps (4 in M x 2 in N),
// warp tile 32x64, mma m16n8k8. M%128==0, N%128==0, K%32==0 here.
// ---------------------------------------------------------------------------
__global__ void __launch_bounds__(256) tf32_gemm_nt(
    const float* __restrict__ A, const float* __restrict__ B,
    const float* __restrict__ bias, float* __restrict__ C,
    int M, int N, int K)
{
    __shared__ uint32_t As[128][36];   // [m][k], pad 36 -> conflict-free frags
    __shared__ uint32_t Bs[128][36];   // [n][k]

    const int tid = threadIdx.x;
    const int m0 = blockIdx.y * 128;
    const int n0 = blockIdx.x * 128;
    const int warpId = tid >> 5;
    const int lane = tid & 31;
    const int g = lane >> 2;          // 0..7
    const int t = lane & 3;           // 0..3
    const int wm = (warpId & 3) * 32; // warp M offset in tile
    const int wn = (warpId >> 2) * 64;// warp N offset in tile

    const int ldRow = tid >> 3;       // 0..31
    const int ldCol = (tid & 7) * 4;  // 0,4,...,28

    const float* Ap = A + (size_t)m0 * K;
    const float* Bp = B + (size_t)n0 * K;

    float c[2][8][4];
#pragma unroll
    for (int mt = 0; mt < 2; mt++)
#pragma unroll
        for (int nt = 0; nt < 8; nt++)
#pragma unroll
            for (int j = 0; j < 4; j++) c[mt][nt][j] = 0.0f;

    for (int k0 = 0; k0 < K; k0 += 32) {
        float4 av[4], bv[4];
#pragma unroll
        for (int r = 0; r < 4; r++) {
            av[r] = *(const float4*)(Ap + (size_t)(ldRow + 32 * r) * K + k0 + ldCol);
            bv[r] = *(const float4*)(Bp + (size_t)(ldRow + 32 * r) * K + k0 + ldCol);
        }
        __syncthreads();
#pragma unroll
        for (int r = 0; r < 4; r++) {
            uint4 at, bt;
            at.x = f2tf32(av[r].x); at.y = f2tf32(av[r].y);
            at.z = f2tf32(av[r].z); at.w = f2tf32(av[r].w);
            bt.x = f2tf32(bv[r].x); bt.y = f2tf32(bv[r].y);
            bt.z = f2tf32(bv[r].z); bt.w = f2tf32(bv[r].w);
            *(uint4*)&As[ldRow + 32 * r][ldCol] = at;
            *(uint4*)&Bs[ldRow + 32 * r][ldCol] = bt;
        }
        __syncthreads();

#pragma unroll
        for (int kk = 0; kk < 4; kk++) {
            const int k = kk * 8;
            uint32_t a[2][4], b[8][2];
#pragma unroll
            for (int mt = 0; mt < 2; mt++) {
                const int rb = wm + mt * 16;
                a[mt][0] = As[rb + g][k + t];
                a[mt][1] = As[rb + g + 8][k + t];
                a[mt][2] = As[rb + g][k + t + 4];
                a[mt][3] = As[rb + g + 8][k + t + 4];
            }
#pragma unroll
            for (int nt = 0; nt < 8; nt++) {
                const int nb = wn + nt * 8;
                b[nt][0] = Bs[nb + g][k + t];
                b[nt][1] = Bs[nb + g][k + t + 4];
            }
#pragma unroll
            for (int mt = 0; mt < 2; mt++)
#pragma unroll
                for (int nt = 0; nt < 8; nt++)
                    mma_tf32(c[mt][nt], a[mt], b[nt]);
        }
    }

    // epilogue: c frag layout — rows g / g+8, cols 2t / 2t+1
#pragma unroll
    for (int mt = 0; mt < 2; mt++) {
        const int r0 = m0 + wm + mt * 16 + g;
#pragma unroll
        for (int nt = 0; nt < 8; nt++) {
            const int col = n0 + wn + nt * 8 + 2 * t;
            const float b0 = bias[col], b1 = bias[col + 1];
            float2 o0 = make_float2(c[mt][nt][0] + b0, c[mt][nt][1] + b1);
            float2 o1 = make_float2(c[mt][nt][2] + b0, c[mt][nt][3] + b1);
            *(float2*)(C + (size_t)r0 * N + col) = o0;
            *(float2*)(C + (size_t)(r0 + 8) * N + col) = o1;
        }
    }
}

// ---------------------------------------------------------------------------
// Flash-style causal attention with fused "shaped" epilogue (unchanged fp32).
// Grid: (T/64, H, B). 128 threads: 16(tx) x 8(ty), micro-tile 8 rows x 4 cols.
// ---------------------------------------------------------------------------
__global__ void __launch_bounds__(128) attn_kernel(
    const float* __restrict__ qkv, float* __restrict__ y,
    const float* __restrict__ alpha_p, const float* __restrict__ beta_p,
    const float* __restrict__ gamma_p)
{
    extern __shared__ float sm[];
    float* Qs = sm;                  // 64 x 68
    float* Ks = sm + 64 * 68;        // 64 x 68
    float* Vs = sm + 2 * 64 * 68;    // 64 x 68
    float* Ps = sm + 3 * 64 * 68;    // 64 x 68

    const int qt = blockIdx.x;
    const int h  = blockIdx.y;
    const int b  = blockIdx.z;
    const int tid = threadIdx.x;
    const int tx = tid & 15;
    const int ty = tid >> 4;
    const int t0 = qt * 64;

    const float alpha = *alpha_p;
    const float beta  = *beta_p;
    const float gamma = *gamma_p;

    const size_t rs = 3 * CC;
    const float* qb = qkv + (size_t)b * TT * rs + h * DD;
    const float* kb = qb + CC;
    const float* vb = qb + 2 * CC;

    const int lr = tid >> 4;
    const int lc = (tid & 15) * 4;

#pragma unroll
    for (int it = 0; it < 8; it++) {
        int r = lr + it * 8;
        float4 qv = *(const float4*)(qb + (size_t)(t0 + r) * rs + lc);
        Qs[(lc + 0) * 68 + r] = qv.x;
        Qs[(lc + 1) * 68 + r] = qv.y;
        Qs[(lc + 2) * 68 + r] = qv.z;
        Qs[(lc + 3) * 68 + r] = qv.w;
    }

    float m[8], l[8], acc[8][4], vsf[4];
#pragma unroll
    for (int i = 0; i < 8; i++) { m[i] = -INFINITY; l[i] = 0.0f; }
#pragma unroll
    for (int i = 0; i < 8; i++)
#pragma unroll
        for (int j = 0; j < 4; j++) acc[i][j] = 0.0f;
    vsf[0] = vsf[1] = vsf[2] = vsf[3] = 0.0f;

    for (int kvt = 0; kvt <= qt; kvt++) {
        const bool diag = (kvt == qt);
        const int s0 = kvt * 64;

        __syncthreads();
#pragma unroll
        for (int it = 0; it < 8; it++) {
            int r = lr + it * 8;
            float4 kk = *(const float4*)(kb + (size_t)(s0 + r) * rs + lc);
            Ks[(lc + 0) * 68 + r] = kk.x;
            Ks[(lc + 1) * 68 + r] = kk.y;
            Ks[(lc + 2) * 68 + r] = kk.z;
            Ks[(lc + 3) * 68 + r] = kk.w;
            float4 vv = *(const float4*)(vb + (size_t)(s0 + r) * rs + lc);
            *(float4*)&Vs[r * 68 + lc] = vv;
        }
        __syncthreads();

        float S[8][4];
#pragma unroll
        for (int i = 0; i < 8; i++)
#pragma unroll
            for (int j = 0; j < 4; j++) S[i][j] = 0.0f;

#pragma unroll 16
        for (int dd = 0; dd < 64; dd++) {
            float4 a0 = *(const float4*)&Qs[dd * 68 + ty * 8];
            float4 a1 = *(const float4*)&Qs[dd * 68 + ty * 8 + 4];
            float4 bv = *(const float4*)&Ks[dd * 68 + tx * 4];
            float a[8] = {a0.x, a0.y, a0.z, a0.w, a1.x, a1.y, a1.z, a1.w};
#pragma unroll
            for (int i = 0; i < 8; i++) {
                S[i][0] = fmaf(a[i], bv.x, S[i][0]);
                S[i][1] = fmaf(a[i], bv.y, S[i][1]);
                S[i][2] = fmaf(a[i], bv.z, S[i][2]);
                S[i][3] = fmaf(a[i], bv.w, S[i][3]);
            }
        }

        const float scale = 0.125f;
#pragma unroll
        for (int i = 0; i < 8; i++)
#pragma unroll
            for (int j = 0; j < 4; j++) {
                float sv = S[i][j] * scale;
                if (diag && (tx * 4 + j > ty * 8 + i)) sv = -INFINITY;
                S[i][j] = sv;
            }

#pragma unroll
        for (int i = 0; i < 8; i++) {
            float rmax = fmaxf(fmaxf(S[i][0], S[i][1]), fmaxf(S[i][2], S[i][3]));
#pragma unroll
            for (int off = 8; off >= 1; off >>= 1)
                rmax = fmaxf(rmax, __shfl_xor_sync(0xffffffffu, rmax, off));
            float mnew = fmaxf(m[i], rmax);
            float corr = __expf(m[i] - mnew);
            float p0 = __expf(S[i][0] - mnew);
            float p1 = __expf(S[i][1] - mnew);
            float p2 = __expf(S[i][2] - mnew);
            float p3 = __expf(S[i][3] - mnew);
            float rsum = (p0 + p1) + (p2 + p3);
#pragma unroll
            for (int off = 8; off >= 1; off >>= 1)
                rsum += __shfl_xor_sync(0xffffffffu, rsum, off);
            l[i] = l[i] * corr + rsum;
            m[i] = mnew;
            acc[i][0] *= corr; acc[i][1] *= corr;
            acc[i][2] *= corr; acc[i][3] *= corr;
            Ps[(tx * 4 + 0) * 68 + ty * 8 + i] = p0;
            Ps[(tx * 4 + 1) * 68 + ty * 8 + i] = p1;
            Ps[(tx * 4 + 2) * 68 + ty * 8 + i] = p2;
            Ps[(tx * 4 + 3) * 68 + ty * 8 + i] = p3;
        }
        __syncthreads();

#pragma unroll 16
        for (int sl = 0; sl < 64; sl++) {
            float4 pa0 = *(const float4*)&Ps[sl * 68 + ty * 8];
            float4 pa1 = *(const float4*)&Ps[sl * 68 + ty * 8 + 4];
            float4 vv = *(const float4*)&Vs[sl * 68 + tx * 4];
            float p[8] = {pa0.x, pa0.y, pa0.z, pa0.w, pa1.x, pa1.y, pa1.z, pa1.w};
#pragma unroll
            for (int i = 0; i < 8; i++) {
                acc[i][0] = fmaf(p[i], vv.x, acc[i][0]);
                acc[i][1] = fmaf(p[i], vv.y, acc[i][1]);
                acc[i][2] = fmaf(p[i], vv.z, acc[i][2]);
                acc[i][3] = fmaf(p[i], vv.w, acc[i][3]);
            }
            if (!diag) {
                vsf[0] += vv.x; vsf[1] += vv.y; vsf[2] += vv.z; vsf[3] += vv.w;
            }
        }
    }

#pragma unroll
    for (int i = 0; i < 8; i++) {
        const int tl = ty * 8 + i;
        const int t  = t0 + tl;
        const float invl = 1.0f / l[i];
        const float invt = 1.0f / (float)(t + 1);
        float vdx = 0.0f, vdy = 0.0f, vdz = 0.0f, vdw = 0.0f;
        for (int sl = 0; sl <= tl; sl++) {
            float4 vv = *(const float4*)&Vs[sl * 68 + tx * 4];
            vdx += vv.x; vdy += vv.y; vdz += vv.z; vdw += vv.w;
        }
        float4 vself = *(const float4*)&Vs[tl * 68 + tx * 4];
        float4 o;
        o.x = beta * acc[i][0] * invl + alpha * vself.x - gamma * (vsf[0] + vdx) * invt;
        o.y = beta * acc[i][1] * invl + alpha * vself.y - gamma * (vsf[1] + vdy) * invt;
        o.z = beta * acc[i][2] * invl + alpha * vself.z - gamma * (vsf[2] + vdz) * invt;
        o.w = beta * acc[i][3] * invl + alpha * vself.w - gamma * (vsf[3] + vdw) * invt;
        *(float4*)(y + ((size_t)b * TT + t) * CC + h * DD + tx * 4) = o;
    }
}

// ---------------------------------------------------------------------------
extern "C" void kernel_launch(void* const* d_in, const int* in_sizes, int n_in,
                              void* d_out, int out_size)
{
    const float* x     = (const float*)d_in[0];
    const float* Wa    = (const float*)d_in[1];
    const float* ba    = (const float*)d_in[2];
    const float* Wp    = (const float*)d_in[3];
    const float* bp    = (const float*)d_in[4];
    const float* alpha = (const float*)d_in[5];
    const float* beta  = (const float*)d_in[6];
    const float* gamma = (const float*)d_in[7];
    float* out = (float*)d_out;

    float* qkv = nullptr;
    float* yb  = nullptr;
    cudaGetSymbolAddress((void**)&qkv, g_qkv);
    cudaGetSymbolAddress((void**)&yb,  g_y);

    const int smem = 4 * 64 * 68 * (int)sizeof(float);
    cudaFuncSetAttribute(attn_kernel,
                         cudaFuncAttributeMaxDynamicSharedMemorySize, smem);

    // 1) qkv = x @ W_attn^T + b_attn
    dim3 g1((3 * CC) / 128, (BB * TT) / 128);
    tf32_gemm_nt<<<g1, 256>>>(x, Wa, ba, qkv, BB * TT, 3 * CC, CC);

    // 2) shaped causal attention
    dim3 ga(TT / 64, HH, BB);
    attn_kernel<<<ga, 128, smem>>>(qkv, yb, alpha, beta, gamma);

    // 3) out = y @ W_proj^T + b_proj
    dim3 g2(CC / 128, (BB * TT) / 128);
    tf32_gemm_nt<<<g2, 256>>>(yb, Wp, bp, out, BB * TT, CC, CC);
}